// round 1
// baseline (speedup 1.0000x reference)
#include <cuda_runtime.h>
#include <cuda_bf16.h>

// Problem constants (fixed for MoELayer_20761871908984)
#define Bq     4
#define Sq     1024
#define Dq     1024
#define Hq     4096
#define Eq     8
#define Kq     2
#define NTOK   (Bq * Sq)        // 4096 tokens
#define MAXROW (NTOK * Kq)      // 8192 max (token, expert) rows

// -------- device-global scratch (no runtime allocation allowed) --------
__device__ int   g_counts[Eq];
__device__ int   g_lists[Eq][NTOK];
__device__ int   g_odd_nonzero;            // !=0 -> assign is int32; ==0 -> int64
__device__ float g_h[(size_t)MAXROW * Hq]; // 128 MB hidden activations

// ---------------------------------------------------------------------
// Kernel 0: zero output + counters
// ---------------------------------------------------------------------
__global__ void k_zero(float* __restrict__ out, int n) {
    int i = blockIdx.x * blockDim.x + threadIdx.x;
    int stride = gridDim.x * blockDim.x;
    float4 z = make_float4(0.f, 0.f, 0.f, 0.f);
    int n4 = n >> 2;
    for (int j = i; j < n4; j += stride)
        reinterpret_cast<float4*>(out)[j] = z;
    // tail (n is a multiple of 4 here, but be safe)
    for (int j = (n4 << 2) + i; j < n; j += stride)
        out[j] = 0.f;
    if (i == 0) {
        g_odd_nonzero = 0;
#pragma unroll
        for (int e = 0; e < Eq; e++) g_counts[e] = 0;
    }
}

// ---------------------------------------------------------------------
// Kernel 1: detect assign element width.
// View buffer as int32. If dtype is int64 (little-endian, values in [0,8)),
// every odd word among the first 2*4096 words is the zero high-word.
// If dtype is int32, odd words are real assignments (~87.5% nonzero of 4096).
// Reading 8192 int32 words is in-bounds for both layouts.
// ---------------------------------------------------------------------
__global__ void k_detect(const int* __restrict__ a32) {
    int i = blockIdx.x * blockDim.x + threadIdx.x;   // [0, 4096)
    int idx = 2 * i + 1;
    if (idx < NTOK * Kq) {
        if (a32[idx] != 0) atomicOr(&g_odd_nonzero, 1);
    }
}

// ---------------------------------------------------------------------
// Kernel 2: build per-expert token lists (dedup within a token's K slots)
// ---------------------------------------------------------------------
__global__ void k_build(const int* __restrict__ a32) {
    int t = blockIdx.x * blockDim.x + threadIdx.x;
    if (t >= NTOK) return;
    int is64 = (g_odd_nonzero == 0);
    unsigned mask = 0;
#pragma unroll
    for (int j = 0; j < Kq; j++) {
        int e;
        if (is64) e = a32[(t * Kq + j) * 2];   // low word of int64
        else      e = a32[t * Kq + j];
        mask |= 1u << (e & (Eq - 1));
    }
    while (mask) {
        int e = __ffs(mask) - 1;
        mask &= mask - 1;
        int p = atomicAdd(&g_counts[e], 1);
        g_lists[e][p] = t;
    }
}

// ---------------------------------------------------------------------
// GEMM1: H_rows = relu( gather(x) @ W1[e] + b1[e] )
// Tile: 64(tokens) x 64(H), BK=16, 256 threads, 4x4 per thread.
// ---------------------------------------------------------------------
__global__ void __launch_bounds__(256)
k_gemm1(const float* __restrict__ x, const float* __restrict__ W1,
        const float* __restrict__ b1) {
    const int e   = blockIdx.z;
    const int cnt = g_counts[e];
    const int m0  = blockIdx.y * 64;
    if (m0 >= cnt) return;
    const int h0  = blockIdx.x * 64;

    int base = 0;
#pragma unroll
    for (int i = 0; i < Eq; i++) base += (i < e) ? g_counts[i] : 0;

    __shared__ __align__(16) float As[16][64];   // [k][m]
    __shared__ __align__(16) float Bs[16][64];   // [k][n]

    const int tid = threadIdx.x;
    const int tx = tid & 15, ty = tid >> 4;

    float acc[4][4];
#pragma unroll
    for (int i = 0; i < 4; i++)
#pragma unroll
        for (int j = 0; j < 4; j++) acc[i][j] = 0.f;

    const float* W = W1 + (size_t)e * Dq * Hq;

    for (int k0 = 0; k0 < Dq; k0 += 16) {
        // load A tile (gathered token rows), store transposed
#pragma unroll
        for (int i = 0; i < 4; i++) {
            int idx = tid + i * 256;
            int r = idx >> 4, c = idx & 15;
            float v = 0.f;
            int row = m0 + r;
            if (row < cnt) {
                int tok = g_lists[e][row];
                v = x[(size_t)tok * Dq + k0 + c];
            }
            As[c][r] = v;
        }
        // load B tile (coalesced along H)
#pragma unroll
        for (int i = 0; i < 4; i++) {
            int idx = tid + i * 256;
            int r = idx >> 6, c = idx & 63;
            Bs[r][c] = W[(size_t)(k0 + r) * Hq + h0 + c];
        }
        __syncthreads();
#pragma unroll
        for (int kk = 0; kk < 16; kk++) {
            float4 av = *reinterpret_cast<const float4*>(&As[kk][ty * 4]);
            float4 bv = *reinterpret_cast<const float4*>(&Bs[kk][tx * 4]);
            float a_[4] = {av.x, av.y, av.z, av.w};
            float b_[4] = {bv.x, bv.y, bv.z, bv.w};
#pragma unroll
            for (int i = 0; i < 4; i++)
#pragma unroll
                for (int j = 0; j < 4; j++) acc[i][j] = fmaf(a_[i], b_[j], acc[i][j]);
        }
        __syncthreads();
    }

    // epilogue: add b1, relu, write g_h
#pragma unroll
    for (int i = 0; i < 4; i++) {
        int row = m0 + ty * 4 + i;
        if (row >= cnt) continue;
        size_t hb = (size_t)(base + row) * Hq + h0 + tx * 4;
        const float* bb = b1 + (size_t)e * Hq + h0 + tx * 4;
        float4 v;
        v.x = fmaxf(acc[i][0] + bb[0], 0.f);
        v.y = fmaxf(acc[i][1] + bb[1], 0.f);
        v.z = fmaxf(acc[i][2] + bb[2], 0.f);
        v.w = fmaxf(acc[i][3] + bb[3], 0.f);
        *reinterpret_cast<float4*>(&g_h[hb]) = v;
    }
}

// ---------------------------------------------------------------------
// GEMM2: out[tok] += (H_rows @ W2[e] + b2[e]) / k   (atomic scatter-add)
// Tile: 64(tokens) x 64(D), BK=16 over Hq=4096.
// ---------------------------------------------------------------------
__global__ void __launch_bounds__(256)
k_gemm2(const float* __restrict__ W2, const float* __restrict__ b2,
        float* __restrict__ out, const int* __restrict__ kp) {
    const int e   = blockIdx.z;
    const int cnt = g_counts[e];
    const int m0  = blockIdx.y * 64;
    if (m0 >= cnt) return;
    const int d0  = blockIdx.x * 64;

    int base = 0;
#pragma unroll
    for (int i = 0; i < Eq; i++) base += (i < e) ? g_counts[i] : 0;

    __shared__ __align__(16) float As[16][64];
    __shared__ __align__(16) float Bs[16][64];

    const int tid = threadIdx.x;
    const int tx = tid & 15, ty = tid >> 4;

    float acc[4][4];
#pragma unroll
    for (int i = 0; i < 4; i++)
#pragma unroll
        for (int j = 0; j < 4; j++) acc[i][j] = 0.f;

    const float* W = W2 + (size_t)e * Hq * Dq;

    for (int k0 = 0; k0 < Hq; k0 += 16) {
#pragma unroll
        for (int i = 0; i < 4; i++) {
            int idx = tid + i * 256;
            int r = idx >> 4, c = idx & 15;
            float v = 0.f;
            int row = m0 + r;
            if (row < cnt)
                v = g_h[(size_t)(base + row) * Hq + k0 + c];
            As[c][r] = v;
        }
#pragma unroll
        for (int i = 0; i < 4; i++) {
            int idx = tid + i * 256;
            int r = idx >> 6, c = idx & 63;
            Bs[r][c] = W[(size_t)(k0 + r) * Dq + d0 + c];
        }
        __syncthreads();
#pragma unroll
        for (int kk = 0; kk < 16; kk++) {
            float4 av = *reinterpret_cast<const float4*>(&As[kk][ty * 4]);
            float4 bv = *reinterpret_cast<const float4*>(&Bs[kk][tx * 4]);
            float a_[4] = {av.x, av.y, av.z, av.w};
            float b_[4] = {bv.x, bv.y, bv.z, bv.w};
#pragma unroll
            for (int i = 0; i < 4; i++)
#pragma unroll
                for (int j = 0; j < 4; j++) acc[i][j] = fmaf(a_[i], b_[j], acc[i][j]);
        }
        __syncthreads();
    }

    int kv = kp ? __ldg(kp) : Kq;          // first 32-bit word == k for i32/i64
    if (kv <= 0) kv = Kq;
    float inv_k = 1.0f / (float)kv;

#pragma unroll
    for (int i = 0; i < 4; i++) {
        int row = m0 + ty * 4 + i;
        if (row >= cnt) continue;
        int tok = g_lists[e][row];
        const float* bb = b2 + (size_t)e * Dq + d0 + tx * 4;
        float* op = out + (size_t)tok * Dq + d0 + tx * 4;
#pragma unroll
        for (int j = 0; j < 4; j++)
            atomicAdd(&op[j], (acc[i][j] + bb[j]) * inv_k);
    }
}

// ---------------------------------------------------------------------
// launch
// ---------------------------------------------------------------------
extern "C" void kernel_launch(void* const* d_in, const int* in_sizes, int n_in,
                              void* d_out, int out_size) {
    const float* x      = (const float*)d_in[0];
    const float* W1     = (const float*)d_in[1];
    const float* b1     = (const float*)d_in[2];
    const float* W2     = (const float*)d_in[3];
    const float* b2     = (const float*)d_in[4];
    const int*   assign = (const int*)d_in[5];
    const int*   kp     = (n_in >= 7) ? (const int*)d_in[6] : nullptr;
    float* out = (float*)d_out;

    // 0: zero output + counters
    k_zero<<<1024, 256>>>(out, out_size);

    // 1: detect assign dtype (int32 vs int64)
    k_detect<<<16, 256>>>(assign);

    // 2: per-expert token lists
    k_build<<<16, 256>>>(assign);

    // 3: grouped GEMM1 -> relu -> g_h
    dim3 g1(Hq / 64, NTOK / 64, Eq);
    k_gemm1<<<g1, 256>>>(x, W1, b1);

    // 4: grouped GEMM2 -> scatter-add into out
    dim3 g2(Dq / 64, NTOK / 64, Eq);
    k_gemm2<<<g2, 256>>>(W2, b2, out, kp);
}

// round 2
// speedup vs baseline: 4.6221x; 4.6221x over previous
#include <cuda_runtime.h>
#include <cuda_bf16.h>
#include <cstdint>

// Problem constants (fixed for MoELayer_20761871908984)
#define Bq     4
#define Sq     1024
#define Dq     1024
#define Hq     4096
#define Eq     8
#define Kq     2
#define NTOK   (Bq * Sq)        // 4096 tokens
#define MAXROW (NTOK * Kq)      // 8192 max (token, expert) rows

// -------- device-global scratch (no runtime allocation allowed) --------
__device__ int   g_counts[Eq];
__device__ int   g_lists[Eq][NTOK];
__device__ int   g_odd_nonzero;            // !=0 -> assign is int32; ==0 -> int64
__device__ float g_h[(size_t)MAXROW * Hq]; // 128 MB hidden activations

// ---------------------------------------------------------------------
// Kernel 0: zero output + counters
// ---------------------------------------------------------------------
__global__ void k_zero(float* __restrict__ out, int n) {
    int i = blockIdx.x * blockDim.x + threadIdx.x;
    int stride = gridDim.x * blockDim.x;
    float4 z = make_float4(0.f, 0.f, 0.f, 0.f);
    int n4 = n >> 2;
    for (int j = i; j < n4; j += stride)
        reinterpret_cast<float4*>(out)[j] = z;
    for (int j = (n4 << 2) + i; j < n; j += stride)
        out[j] = 0.f;
    if (i == 0) {
        g_odd_nonzero = 0;
#pragma unroll
        for (int e = 0; e < Eq; e++) g_counts[e] = 0;
    }
}

// ---------------------------------------------------------------------
// Kernel 1: detect assign element width (int32 vs int64, little-endian)
// ---------------------------------------------------------------------
__global__ void k_detect(const int* __restrict__ a32) {
    int i = blockIdx.x * blockDim.x + threadIdx.x;   // [0, 4096)
    int idx = 2 * i + 1;
    if (idx < NTOK * Kq) {
        if (a32[idx] != 0) atomicOr(&g_odd_nonzero, 1);
    }
}

// ---------------------------------------------------------------------
// Kernel 2: build per-expert token lists (dedup within a token's K slots)
// ---------------------------------------------------------------------
__global__ void k_build(const int* __restrict__ a32) {
    int t = blockIdx.x * blockDim.x + threadIdx.x;
    if (t >= NTOK) return;
    int is64 = (g_odd_nonzero == 0);
    unsigned mask = 0;
#pragma unroll
    for (int j = 0; j < Kq; j++) {
        int e;
        if (is64) e = a32[(t * Kq + j) * 2];   // low word of int64
        else      e = a32[t * Kq + j];
        mask |= 1u << (e & (Eq - 1));
    }
    while (mask) {
        int e = __ffs(mask) - 1;
        mask &= mask - 1;
        int p = atomicAdd(&g_counts[e], 1);
        g_lists[e][p] = t;
    }
}

// ---------------------------------------------------------------------
// tf32 tensor-core grouped GEMM (mma.sync.m16n8k8)
//   CTA tile 128(M) x 128(N), BK=16, 256 threads, 8 warps of 64x32.
//   G1: A = gather(x) [rows, 1024], B = W1[e] [1024, 4096], out -> relu -> g_h
//   G2: A = g_h rows  [rows, 4096], B = W2[e] [4096, 1024], out -> atomicAdd
// ---------------------------------------------------------------------

__device__ __forceinline__ unsigned f2tf32(float f) {
    unsigned r;
    asm volatile("cvt.rna.tf32.f32 %0, %1;\n" : "=r"(r) : "f"(f));
    return r;
}

__device__ __forceinline__ void mma_tf32(float& d0, float& d1, float& d2, float& d3,
                                         unsigned a0, unsigned a1, unsigned a2, unsigned a3,
                                         unsigned b0, unsigned b1) {
    asm volatile(
        "mma.sync.aligned.m16n8k8.row.col.f32.tf32.tf32.f32 "
        "{%0,%1,%2,%3},{%4,%5,%6,%7},{%8,%9},{%0,%1,%2,%3};\n"
        : "+f"(d0), "+f"(d1), "+f"(d2), "+f"(d3)
        : "r"(a0), "r"(a1), "r"(a2), "r"(a3), "r"(b0), "r"(b1));
}

__device__ __forceinline__ void cp_async16(uint32_t smem_addr, const void* gptr, int pbytes) {
    asm volatile("cp.async.cg.shared.global [%0], [%1], 16, %2;\n"
                 :: "r"(smem_addr), "l"(gptr), "r"(pbytes));
}
__device__ __forceinline__ void cp_commit() { asm volatile("cp.async.commit_group;\n"); }
__device__ __forceinline__ void cp_wait1()  { asm volatile("cp.async.wait_group 1;\n"); }
__device__ __forceinline__ void cp_wait0()  { asm volatile("cp.async.wait_group 0;\n"); }

#define ASTRIDE 20    // floats per A smem row (16 + pad 4): conflict-free frags
#define BSTRIDE 136   // floats per B smem row (128 + pad 8): conflict-free frags

template<int KD, int ND, bool G1>
__global__ void __launch_bounds__(256)
k_gemm_tc(const float* __restrict__ Ain,      // G1: x ;  G2: g_h (via global)
          const float* __restrict__ W,        // [E][KD][ND]
          const float* __restrict__ bias,     // [E][ND]
          float* __restrict__ out,            // G2 only
          const int* __restrict__ kp)         // G2 only
{
    const int e   = blockIdx.z;
    const int cnt = g_counts[e];
    const int m0  = blockIdx.y * 128;
    if (m0 >= cnt) return;
    const int n0  = blockIdx.x * 128;

    int base = 0;
#pragma unroll
    for (int i = 0; i < Eq; i++) base += (i < e) ? g_counts[i] : 0;

    __shared__ __align__(16) float As[2][128][ASTRIDE];
    __shared__ __align__(16) float Bs[2][16][BSTRIDE];
    __shared__ int toks[128];

    const int tid  = threadIdx.x;
    const int lane = tid & 31;
    const int wid  = tid >> 5;
    const int wm   = wid >> 2;     // 0..1  (64-row band)
    const int wn   = wid & 3;      // 0..3  (32-col band)
    const int g    = lane >> 2;    // 0..7
    const int c    = lane & 3;     // 0..3

    // token list + validity for this M tile
    if (tid < 128) {
        int row = m0 + tid;
        toks[tid] = (row < cnt) ? g_lists[e][row] : 0;
    }
    __syncthreads();

    const float* Wp = W + (size_t)e * KD * ND;
    const int NK = KD / 16;

    // ---- stage loader ----
    auto load_stage = [&](int kt, int buf) {
        const int k0 = kt * 16;
        // A: 128 rows x 16 k = 512 x 16B chunks
#pragma unroll
        for (int i = 0; i < 2; i++) {
            int idx = tid + i * 256;
            int kq  = idx >> 7;          // 0..3
            int m   = idx & 127;
            int row = m0 + m;
            int valid = (row < cnt);
            const float* src;
            if (G1) {
                src = Ain + (size_t)toks[m] * KD + k0 + 4 * kq;
            } else {
                size_t r = valid ? (size_t)(base + row) : 0;
                src = g_h + r * KD + k0 + 4 * kq;
            }
            uint32_t dst = (uint32_t)__cvta_generic_to_shared(&As[buf][m][4 * kq]);
            cp_async16(dst, src, valid ? 16 : 0);
        }
        // B: 16 k x 128 n = 512 x 16B chunks
#pragma unroll
        for (int i = 0; i < 2; i++) {
            int idx = tid + i * 256;
            int k   = idx >> 5;          // 0..15
            int nq  = idx & 31;          // 0..31
            const float* src = Wp + (size_t)(k0 + k) * ND + n0 + 4 * nq;
            uint32_t dst = (uint32_t)__cvta_generic_to_shared(&Bs[buf][k][4 * nq]);
            cp_async16(dst, src, 16);
        }
        cp_commit();
    };

    float acc[4][4][4];
#pragma unroll
    for (int i = 0; i < 4; i++)
#pragma unroll
        for (int j = 0; j < 4; j++)
#pragma unroll
            for (int r = 0; r < 4; r++) acc[i][j][r] = 0.f;

    load_stage(0, 0);

    for (int kt = 0; kt < NK; kt++) {
        const int buf = kt & 1;
        if (kt + 1 < NK) {
            load_stage(kt + 1, buf ^ 1);
            cp_wait1();
        } else {
            cp_wait0();
        }
        __syncthreads();

#pragma unroll
        for (int k8 = 0; k8 < 2; k8++) {
            const int kb = k8 * 8;
            unsigned af[4][4], bf[4][2];
#pragma unroll
            for (int i = 0; i < 4; i++) {
                int r0 = wm * 64 + i * 16 + g;
                af[i][0] = f2tf32(As[buf][r0    ][kb + c    ]);
                af[i][1] = f2tf32(As[buf][r0 + 8][kb + c    ]);
                af[i][2] = f2tf32(As[buf][r0    ][kb + c + 4]);
                af[i][3] = f2tf32(As[buf][r0 + 8][kb + c + 4]);
            }
#pragma unroll
            for (int j = 0; j < 4; j++) {
                int nn = wn * 32 + j * 8 + g;
                bf[j][0] = f2tf32(Bs[buf][kb + c    ][nn]);
                bf[j][1] = f2tf32(Bs[buf][kb + c + 4][nn]);
            }
#pragma unroll
            for (int i = 0; i < 4; i++)
#pragma unroll
                for (int j = 0; j < 4; j++)
                    mma_tf32(acc[i][j][0], acc[i][j][1], acc[i][j][2], acc[i][j][3],
                             af[i][0], af[i][1], af[i][2], af[i][3],
                             bf[j][0], bf[j][1]);
        }
        __syncthreads();
    }

    // ---- epilogue ----
    if (G1) {
        // relu(acc + b1) -> g_h
#pragma unroll
        for (int j = 0; j < 4; j++) {
            int col = n0 + wn * 32 + j * 8 + 2 * c;
            float bv0 = __ldg(bias + (size_t)e * ND + col);
            float bv1 = __ldg(bias + (size_t)e * ND + col + 1);
#pragma unroll
            for (int i = 0; i < 4; i++) {
                int r0 = m0 + wm * 64 + i * 16 + g;
                if (r0 < cnt) {
                    float2 v;
                    v.x = fmaxf(acc[i][j][0] + bv0, 0.f);
                    v.y = fmaxf(acc[i][j][1] + bv1, 0.f);
                    *reinterpret_cast<float2*>(&g_h[(size_t)(base + r0) * ND + col]) = v;
                }
                int r1 = r0 + 8;
                if (r1 < cnt) {
                    float2 v;
                    v.x = fmaxf(acc[i][j][2] + bv0, 0.f);
                    v.y = fmaxf(acc[i][j][3] + bv1, 0.f);
                    *reinterpret_cast<float2*>(&g_h[(size_t)(base + r1) * ND + col]) = v;
                }
            }
        }
    } else {
        int kv = kp ? __ldg(kp) : Kq;
        if (kv <= 0) kv = Kq;
        float inv_k = 1.0f / (float)kv;
#pragma unroll
        for (int j = 0; j < 4; j++) {
            int col = n0 + wn * 32 + j * 8 + 2 * c;
            float bv0 = __ldg(bias + (size_t)e * ND + col);
            float bv1 = __ldg(bias + (size_t)e * ND + col + 1);
#pragma unroll
            for (int i = 0; i < 4; i++) {
                int r0 = m0 + wm * 64 + i * 16 + g;
                if (r0 < cnt) {
                    float* op = out + (size_t)toks[r0 - m0] * ND + col;
                    atomicAdd(op,     (acc[i][j][0] + bv0) * inv_k);
                    atomicAdd(op + 1, (acc[i][j][1] + bv1) * inv_k);
                }
                int r1 = r0 + 8;
                if (r1 < cnt) {
                    float* op = out + (size_t)toks[r1 - m0] * ND + col;
                    atomicAdd(op,     (acc[i][j][2] + bv0) * inv_k);
                    atomicAdd(op + 1, (acc[i][j][3] + bv1) * inv_k);
                }
            }
        }
    }
}

// ---------------------------------------------------------------------
// launch
// ---------------------------------------------------------------------
extern "C" void kernel_launch(void* const* d_in, const int* in_sizes, int n_in,
                              void* d_out, int out_size) {
    const float* x      = (const float*)d_in[0];
    const float* W1     = (const float*)d_in[1];
    const float* b1     = (const float*)d_in[2];
    const float* W2     = (const float*)d_in[3];
    const float* b2     = (const float*)d_in[4];
    const int*   assign = (const int*)d_in[5];
    const int*   kp     = (n_in >= 7) ? (const int*)d_in[6] : nullptr;
    float* out = (float*)d_out;

    k_zero<<<1024, 256>>>(out, out_size);
    k_detect<<<16, 256>>>(assign);
    k_build<<<16, 256>>>(assign);

    // GEMM1: [rows,1024] @ [1024,4096] -> relu -> g_h
    dim3 g1(Hq / 128, NTOK / 128, Eq);
    k_gemm_tc<Dq, Hq, true><<<g1, 256>>>(x, W1, b1, nullptr, nullptr);

    // GEMM2: [rows,4096] @ [4096,1024] -> scatter-add out
    dim3 g2(Dq / 128, NTOK / 128, Eq);
    k_gemm_tc<Hq, Dq, false><<<g2, 256>>>(nullptr, W2, b2, out, kp);
}